// round 14
// baseline (speedup 1.0000x reference)
#include <cuda_runtime.h>
#include <cuda_fp16.h>
#include <cstdint>

#define B_SZ 1024
#define F_SZ 256
#define D_SZ 64
#define NFULL (F_SZ * D_SZ)
#define GRID_ALL 148

// ---------------- device scratch ----------------
__device__ float    g_qkv[3 * F_SZ * D_SZ];    // qkv[t][f][d]
__device__ float    g_trans[2 * F_SZ * D_SZ];  // trans[t][f][d]
__device__ __half   g_Mh[F_SZ * F_SZ];         // gated cross, fp16
__device__ unsigned g_bcnt[2];                 // barrier arrive counters
__device__ unsigned g_bgen[2];                 // barrier generations (monotonic)

// ---------------- smem layout (bytes) ----------------
#define A_RB 528                   // M row: 256 halfs + 8 pad
#define Z_RB 144                   // Z row: 64 halfs + 8 pad
#define SM_A 0                     // 256*528 = 135168
#define SM_Z 135168                // 2 Z buffers
#define Z_BYTES (F_SZ * Z_RB)      // 36864
#define SM_S1 (SM_Z + 2 * Z_BYTES) // 208896: 7*256 fp32
#define SM_SA (SM_S1 + 7 * 256 * 4)// 216064: 7*256 fp32
#define SMEM_TOTAL (SM_SA + 7 * 256 * 4)  // 223232

// ---------------- helpers ----------------
__device__ __forceinline__ uint32_t smem_u32(const void* p) {
    uint32_t a;
    asm("{ .reg .u64 t; cvta.to.shared.u64 t, %1; cvt.u32.u64 %0, t; }"
        : "=r"(a) : "l"(p));
    return a;
}
#define LDSM4(r, a) \
    asm volatile("ldmatrix.sync.aligned.m8n8.x4.shared.b16 {%0,%1,%2,%3}, [%4];" \
                 : "=r"((r)[0]), "=r"((r)[1]), "=r"((r)[2]), "=r"((r)[3]) : "r"(a))
#define LDSM4T(r, a) \
    asm volatile("ldmatrix.sync.aligned.m8n8.x4.trans.shared.b16 {%0,%1,%2,%3}, [%4];" \
                 : "=r"((r)[0]), "=r"((r)[1]), "=r"((r)[2]), "=r"((r)[3]) : "r"(a))
#define HMMA(d, a, b0, b1) \
    asm volatile("mma.sync.aligned.m16n8k16.row.col.f32.f16.f16.f32 " \
                 "{%0,%1,%2,%3}, {%4,%5,%6,%7}, {%8,%9}, {%0,%1,%2,%3};" \
                 : "+f"((d)[0]), "+f"((d)[1]), "+f"((d)[2]), "+f"((d)[3]) \
                 : "r"((a)[0]), "r"((a)[1]), "r"((a)[2]), "r"((a)[3]), \
                   "r"(b0), "r"(b1))

__device__ __forceinline__ uint32_t pack2h(float a, float b) {
    __half2 h = __floats2half2_rn(a, b);
    return *(uint32_t*)&h;
}

// sense-reversal grid barrier; safe for repeated graph replays (gen monotonic,
// count self-resets). All GRID_ALL CTAs are resident (1 CTA/SM), so no deadlock.
__device__ __forceinline__ void grid_bar(int id) {
    __syncthreads();
    if (threadIdx.x == 0) {
        __threadfence();
        unsigned gen = atomicAdd(&g_bgen[id], 0u);
        unsigned arrived = atomicAdd(&g_bcnt[id], 1u);
        if (arrived == GRID_ALL - 1) {
            atomicExch(&g_bcnt[id], 0u);
            __threadfence();
            atomicAdd(&g_bgen[id], 1u);
        } else {
            while (atomicAdd(&g_bgen[id], 0u) == gen) __nanosleep(32);
        }
        __threadfence();
    }
    __syncthreads();
}

// build one Z element (8 halfs): Z[j][dq*8..+8) = s1[j] * q2[j][...]
__device__ __forceinline__ void z_elem(char* zbuf, const float* q2,
                                       const float* s1p, int idx) {
    int j = idx >> 3, dq = idx & 7;
    float s1 = s1p[j];                      // smem
    const float4* qp = (const float4*)(q2 + j * 64) + dq * 2;
    float4 qa = qp[0], qb = qp[1];
    uint4 v;
    v.x = pack2h(qa.x * s1, qa.y * s1);
    v.y = pack2h(qa.z * s1, qa.w * s1);
    v.z = pack2h(qb.x * s1, qb.y * s1);
    v.w = pack2h(qb.z * s1, qb.w * s1);
    *(uint4*)(zbuf + j * Z_RB + dq * 16) = v;
}

// ---------------- the single fused kernel ----------------
__global__ void __launch_bounds__(512, 1)
k_all(const float* __restrict__ feature, const float* __restrict__ ind,
      const float* __restrict__ Wqk, const float* __restrict__ Wqkv,
      float* __restrict__ out) {
    extern __shared__ char sm[];
    uint32_t sb = smem_u32(sm);
    int tid = threadIdx.x, c = blockIdx.x;
    int w = tid >> 5, lane = tid & 31;

    // ======== Phase 1: qkv/trans = indicator @ W (distributed) ========
    {
        int grp = tid >> 6, e = tid & 63;
        for (int r = c + grp * GRID_ALL; r < 1280; r += 8 * GRID_ALL) {
            int m = r >> 8, f = r & 255;
            const float* W = (m < 3) ? (Wqkv + m * 4096) : (Wqk + (m - 3) * 4096);
            const float* indf = ind + f * 64;
            float acc = 0.f;
#pragma unroll 16
            for (int d = 0; d < 64; d++)
                acc = fmaf(__ldg(indf + d), __ldg(W + d * 64 + e), acc);
            if (m < 3) g_qkv[m * 16384 + f * 64 + e] = acc;
            else       g_trans[(m - 3) * 16384 + f * 64 + e] = acc;
        }
    }
    grid_bar(0);

    // ======== Phase 2: gate rows -> g_Mh (distributed over i) ========
    {
        float* scr = (float*)(sm + SM_Z);   // q1i[64] at scr, t0i[64] at scr+64
        for (int i = c; i < 256; i += GRID_ALL) {
            __syncthreads();
            if (tid < 64) scr[tid] = g_qkv[16384 + i * 64 + tid];
            else if (tid < 128) scr[tid] = g_trans[i * 64 + (tid - 64)];
            __syncthreads();
#pragma unroll
            for (int jj = 0; jj < 16; jj++) {
                int j = w * 16 + jj;
                float cc = scr[lane] * g_qkv[j * 64 + lane]
                         + scr[lane + 32] * g_qkv[j * 64 + lane + 32];
                float gl = scr[64 + lane] * g_trans[16384 + j * 64 + lane]
                         + scr[64 + lane + 32] * g_trans[16384 + j * 64 + lane + 32];
#pragma unroll
                for (int o = 16; o > 0; o >>= 1) {
                    cc += __shfl_xor_sync(0xFFFFFFFFu, cc, o);
                    gl += __shfl_xor_sync(0xFFFFFFFFu, gl, o);
                }
                if (lane == 0)
                    g_Mh[i * 256 + j] = __float2half_rn((gl > 0.f) ? cc : 0.f);
            }
        }
    }
    grid_bar(1);

    // ======== Phase 3a: local S1/SA for own batches (smem) ========
    int b0 = (c * B_SZ) / GRID_ALL, b1 = ((c + 1) * B_SZ) / GRID_ALL;
    int NB = b1 - b0;
    float* sS1 = (float*)(sm + SM_S1);
    float* sSA = (float*)(sm + SM_SA);
    {
        int grp = tid >> 4, ll = tid & 15;   // 32 groups of 16 lanes
        for (int t = 0; t < NB; t++) {
            const float* fb = feature + (size_t)(b0 + t) * 16384;
#pragma unroll
            for (int ii = 0; ii < 8; ii++) {
                int i = grp + ii * 32;
                const float4* qp = (const float4*)(g_qkv + i * 64) + ll;
                float4 q0 = qp[0];
                float4 q1 = qp[4096];
                float4 q2 = qp[8192];
                float4 f = *((const float4*)(fb + i * 64) + ll);
                float d0 = f.x * q0.x + f.y * q0.y + f.z * q0.z + f.w * q0.w;
                float d1 = f.x * q1.x + f.y * q1.y + f.z * q1.z + f.w * q1.w;
                float d2 = f.x * q2.x + f.y * q2.y + f.z * q2.z + f.w * q2.w;
#pragma unroll
                for (int o = 8; o > 0; o >>= 1) {
                    d0 += __shfl_xor_sync(0xFFFFFFFFu, d0, o);
                    d1 += __shfl_xor_sync(0xFFFFFFFFu, d1, o);
                    d2 += __shfl_xor_sync(0xFFFFFFFFu, d2, o);
                }
                if (ll == 0) {
                    sS1[t * 256 + i] = d1;
                    sSA[t * 256 + i] = d0 * d2;
                }
            }
        }
    }
    __syncthreads();

    // ======== Phase 3b: load M into smem ========
    {
        const uint4* msrc = (const uint4*)g_Mh;
        for (int i = tid; i < 8192; i += 512) {
            int r = i >> 5, c8 = i & 31;
            *(uint4*)(sm + SM_A + r * A_RB + c8 * 16) = msrc[i];
        }
    }

    // warp geometry: 16 warps, tile (32 m) x (32 n), full K=256
    int m0 = (w >> 1) * 32, n0 = (w & 1) * 32;
    int g = lane >> 2, t4 = lane & 3;
    uint32_t aBase = sb + SM_A + (uint32_t)(m0 + (lane & 15)) * A_RB
                     + (uint32_t)(lane >> 4) * 16;
    uint32_t bBase0 = sb + SM_Z + (uint32_t)(lane & 15) * Z_RB
                      + (uint32_t)(n0 + 8 * (lane >> 4)) * 2;
    const float* q2 = g_qkv + 2 * F_SZ * D_SZ;

    // initial Z build for batch 0 into buffer 0
    for (int idx = tid; idx < 2048; idx += 512)
        z_elem(sm + SM_Z, q2, sS1, idx);
    __syncthreads();

    // ======== Phase 3c: mainloop (R11 structure, smem S sources) ========
    for (int t = 0; t < NB; t++) {
        int cur = t & 1;
        uint32_t bBase = bBase0 + (uint32_t)cur * Z_BYTES;
        char* znxt = sm + SM_Z + (cur ^ 1) * Z_BYTES;
        const float* s1n = sS1 + (t + 1) * 256;
        bool doNext = (t + 1 < NB);

        float acc[8][4];
#pragma unroll
        for (int i = 0; i < 8; i++)
#pragma unroll
            for (int q = 0; q < 4; q++) acc[i][q] = 0.f;

#pragma unroll
        for (int k = 0; k < 16; k++) {
            uint32_t kA = (uint32_t)k * 32;
            uint32_t kB = (uint32_t)k * 16 * Z_RB;
            uint32_t a0[4], a1[4], bq0[4], bq1[4];
            LDSM4(a0, aBase + kA);
            LDSM4(a1, aBase + 16 * A_RB + kA);
            LDSM4T(bq0, bBase + kB);
            LDSM4T(bq1, bBase + kB + 32);

            HMMA(acc[0], a0, bq0[0], bq0[1]);
            HMMA(acc[1], a0, bq0[2], bq0[3]);
            HMMA(acc[2], a0, bq1[0], bq1[1]);
            HMMA(acc[3], a0, bq1[2], bq1[3]);
            HMMA(acc[4], a1, bq0[0], bq0[1]);
            HMMA(acc[5], a1, bq0[2], bq0[3]);
            HMMA(acc[6], a1, bq1[0], bq1[1]);
            HMMA(acc[7], a1, bq1[2], bq1[3]);

            if ((k & 3) == 2) {                  // k = 2, 6, 10, 14
                if (doNext) z_elem(znxt, q2, s1n, (k >> 2) * 512 + tid);
            }
        }

        // epilogue: scale by SA (smem), store
        const float* sap = sSA + t * 256;
        float* ob = out + (size_t)(b0 + t) * NFULL;
#pragma unroll
        for (int mt = 0; mt < 2; mt++) {
            int r0 = m0 + mt * 16 + g;
            float f0 = sap[r0], f1 = sap[r0 + 8];
#pragma unroll
            for (int nt = 0; nt < 4; nt++) {
                float* a = acc[mt * 4 + nt];
                int col = n0 + nt * 8 + 2 * t4;
                *(float2*)(ob + r0 * 64 + col) =
                    make_float2(a[0] * f0, a[1] * f0);
                *(float2*)(ob + (r0 + 8) * 64 + col) =
                    make_float2(a[2] * f1, a[3] * f1);
            }
        }
        __syncthreads();   // Z[t+1] fully written before next iter consumes it
    }
}

// ---------------- launch ----------------
extern "C" void kernel_launch(void* const* d_in, const int* in_sizes, int n_in,
                              void* d_out, int out_size) {
    const float *feature = nullptr, *indicator = nullptr;
    const float *Wqk = nullptr, *Wqkv = nullptr;
    for (int k = 0; k < n_in; k++) {
        switch (in_sizes[k]) {
            case B_SZ * F_SZ * D_SZ: feature   = (const float*)d_in[k]; break;
            case F_SZ * D_SZ:        indicator = (const float*)d_in[k]; break;
            case 2 * D_SZ * D_SZ:    Wqk       = (const float*)d_in[k]; break;
            case 3 * D_SZ * D_SZ:    Wqkv      = (const float*)d_in[k]; break;
        }
    }
    float* out = (float*)d_out;

    cudaFuncSetAttribute(k_all, cudaFuncAttributeMaxDynamicSharedMemorySize,
                         SMEM_TOTAL);
    k_all<<<GRID_ALL, 512, SMEM_TOTAL>>>(feature, indicator, Wqk, Wqkv, out);
}

// round 15
// speedup vs baseline: 1.2793x; 1.2793x over previous
#include <cuda_runtime.h>
#include <cuda_fp16.h>
#include <cstdint>

#define B_SZ 1024
#define F_SZ 256
#define D_SZ 64
#define NFULL (F_SZ * D_SZ)
#define GRID_MAIN 296            // 2 CTAs per SM
#define NUNITS 2048              // 2 halves x 1024 batches, h-major

// ---------------- device scratch ----------------
__device__ float  g_qkv[3 * F_SZ * D_SZ];    // qkv[t][f][d]
__device__ float  g_trans[2 * F_SZ * D_SZ];  // trans[t][f][d]
__device__ float  g_S1[B_SZ * F_SZ];         // s1[b][j]
__device__ float  g_SA[B_SZ * F_SZ];         // s0*s2 [b][i]
__device__ __half g_Mh[F_SZ * F_SZ];         // gated cross, fp16

// ---------------- smem layout for k_main (bytes) ----------------
#define A_RB 528                  // M row: 256 halfs + 8 pad
#define Z_RB 144                  // Z row: 64 halfs + 8 pad
#define SM_A 0                    // 128 * 528 = 67584 (one M half)
#define SM_Z 67584                // 256 * 144 = 36864 (single buffer)
#define SMEM_TOTAL (SM_Z + F_SZ * Z_RB)   // 104448 -> 2 CTAs/SM

// ---------------- helpers ----------------
__device__ __forceinline__ uint32_t smem_u32(const void* p) {
    uint32_t a;
    asm("{ .reg .u64 t; cvta.to.shared.u64 t, %1; cvt.u32.u64 %0, t; }"
        : "=r"(a) : "l"(p));
    return a;
}
#define LDSM4(r, a) \
    asm volatile("ldmatrix.sync.aligned.m8n8.x4.shared.b16 {%0,%1,%2,%3}, [%4];" \
                 : "=r"((r)[0]), "=r"((r)[1]), "=r"((r)[2]), "=r"((r)[3]) : "r"(a))
#define LDSM4T(r, a) \
    asm volatile("ldmatrix.sync.aligned.m8n8.x4.trans.shared.b16 {%0,%1,%2,%3}, [%4];" \
                 : "=r"((r)[0]), "=r"((r)[1]), "=r"((r)[2]), "=r"((r)[3]) : "r"(a))
#define HMMA(d, a, b0, b1) \
    asm volatile("mma.sync.aligned.m16n8k16.row.col.f32.f16.f16.f32 " \
                 "{%0,%1,%2,%3}, {%4,%5,%6,%7}, {%8,%9}, {%0,%1,%2,%3};" \
                 : "+f"((d)[0]), "+f"((d)[1]), "+f"((d)[2]), "+f"((d)[3]) \
                 : "r"((a)[0]), "r"((a)[1]), "r"((a)[2]), "r"((a)[3]), \
                   "r"(b0), "r"(b1))

__device__ __forceinline__ uint32_t pack2h(float a, float b) {
    __half2 h = __floats2half2_rn(a, b);
    return *(uint32_t*)&h;
}

// build one Z element (8 halfs = 16 bytes): Z[j][dq*8..+8)
__device__ __forceinline__ void z_elem(char* zbuf, const float* q2,
                                       const float* s1p, int idx) {
    int j = idx >> 3, dq = idx & 7;
    float s1 = __ldg(s1p + j);
    const float4* qp = (const float4*)(q2 + j * 64) + dq * 2;
    float4 qa = qp[0], qb = qp[1];
    uint4 v;
    v.x = pack2h(qa.x * s1, qa.y * s1);
    v.y = pack2h(qa.z * s1, qa.w * s1);
    v.z = pack2h(qb.x * s1, qb.y * s1);
    v.w = pack2h(qb.z * s1, qb.w * s1);
    *(uint4*)(zbuf + j * Z_RB + dq * 16) = v;
}

// ---------------- K1: qkv / trans = indicator @ W ----------------
__global__ void k_qkv(const float* __restrict__ ind,
                      const float* __restrict__ Wqk,
                      const float* __restrict__ Wqkv) {
    int m = blockIdx.y;
    int fl = threadIdx.x >> 6, e = threadIdx.x & 63;
    int f = blockIdx.x * 4 + fl;
    __shared__ float indS[4 * D_SZ];
    indS[threadIdx.x] = ind[f * D_SZ + e];
    __syncthreads();
    const float* W = (m < 3) ? (Wqkv + m * D_SZ * D_SZ)
                             : (Wqk + (m - 3) * D_SZ * D_SZ);
    float acc = 0.f;
#pragma unroll
    for (int d = 0; d < D_SZ; d++) acc = fmaf(indS[fl * 64 + d], W[d * D_SZ + e], acc);
    if (m < 3) g_qkv[m * F_SZ * D_SZ + f * D_SZ + e] = acc;
    else       g_trans[(m - 3) * F_SZ * D_SZ + f * D_SZ + e] = acc;
}

// ---------------- K2: merged gate + s kernel ----------------
__global__ void __launch_bounds__(256) k_prep(const float* __restrict__ feature) {
    int tid = threadIdx.x, w = tid >> 5, l = tid & 31;
    if (blockIdx.x < 256) {
        int i = blockIdx.x;
        __shared__ float q1i[D_SZ], t0i[D_SZ];
        if (tid < 64) q1i[tid] = g_qkv[F_SZ * D_SZ + i * D_SZ + tid];
        else if (tid < 128) t0i[tid - 64] = g_trans[i * D_SZ + (tid - 64)];
        __syncthreads();
        const float* q0 = g_qkv;
        const float* t1 = g_trans + F_SZ * D_SZ;
        for (int jj = 0; jj < 32; jj++) {
            int j = w * 32 + jj;
            float c  = q1i[l] * q0[j * D_SZ + l] + q1i[l + 32] * q0[j * D_SZ + l + 32];
            float gl = t0i[l] * t1[j * D_SZ + l] + t0i[l + 32] * t1[j * D_SZ + l + 32];
#pragma unroll
            for (int o = 16; o > 0; o >>= 1) {
                c  += __shfl_xor_sync(0xFFFFFFFFu, c, o);
                gl += __shfl_xor_sync(0xFFFFFFFFu, gl, o);
            }
            if (l == 0)
                g_Mh[i * F_SZ + j] = __float2half_rn((gl > 0.f) ? c : 0.f);
        }
    } else {
        int b0 = (blockIdx.x - 256) * 2;
        int hb = l >> 4, ll = l & 15;
        int b = b0 + hb;
        for (int ii = 0; ii < 32; ii++) {
            int i = w * 32 + ii;
            const float4* qp = (const float4*)(g_qkv + i * D_SZ) + ll;
            float4 q0 = qp[0];
            float4 q1 = qp[(F_SZ * D_SZ) / 4];
            float4 q2 = qp[(2 * F_SZ * D_SZ) / 4];
            float4 f = *((const float4*)(feature + (size_t)b * (F_SZ * D_SZ)
                                         + i * D_SZ) + ll);
            float d0 = f.x * q0.x + f.y * q0.y + f.z * q0.z + f.w * q0.w;
            float d1 = f.x * q1.x + f.y * q1.y + f.z * q1.z + f.w * q1.w;
            float d2 = f.x * q2.x + f.y * q2.y + f.z * q2.z + f.w * q2.w;
#pragma unroll
            for (int o = 8; o > 0; o >>= 1) {
                d0 += __shfl_xor_sync(0xFFFFFFFFu, d0, o);
                d1 += __shfl_xor_sync(0xFFFFFFFFu, d1, o);
                d2 += __shfl_xor_sync(0xFFFFFFFFu, d2, o);
            }
            if (ll == 0) {
                g_S1[b * F_SZ + i] = d1;
                g_SA[b * F_SZ + i] = d0 * d2;
            }
        }
    }
}

// ---------------- K3: fp16 HMMA main kernel, 2 CTAs/SM ----------------
// Unit u = h*1024 + b (h-major). CTA c handles [c*2048/296, (c+1)*2048/296).
// 256 threads, 8 warps: warp tile 32x32 over 128(m-half) x 64(n), full K=256.
// Single Z buffer; cross-CTA overlap hides Z-build/sync/epilogue.
__global__ void __launch_bounds__(256, 2)
k_main(float* __restrict__ out) {
    extern __shared__ char sm[];
    uint32_t sb = smem_u32(sm);
    int tid = threadIdx.x, w = tid >> 5, lane = tid & 31;
    int c = blockIdx.x;
    int u0 = (c * NUNITS) / GRID_MAIN, u1 = ((c + 1) * NUNITS) / GRID_MAIN;

    int m0 = (w >> 1) * 32, n0 = (w & 1) * 32;
    int g = lane >> 2, t4 = lane & 3;
    uint32_t aBase = sb + SM_A + (uint32_t)(m0 + (lane & 15)) * A_RB
                     + (uint32_t)(lane >> 4) * 16;
    uint32_t bBase = sb + SM_Z + (uint32_t)(lane & 15) * Z_RB
                     + (uint32_t)(n0 + 8 * (lane >> 4)) * 2;
    const float* q2 = g_qkv + 2 * F_SZ * D_SZ;

    int curH = -1;
    for (int u = u0; u < u1; u++) {
        int h = u >> 10, b = u & 1023;

        __syncthreads();   // prior readers of Z (and A) done
        if (h != curH) {
            const uint4* msrc = (const uint4*)(g_Mh + (size_t)h * 128 * F_SZ);
            for (int i = tid; i < 4096; i += 256) {
                int r = i >> 5, c8 = i & 31;
                *(uint4*)(sm + SM_A + r * A_RB + c8 * 16) = msrc[i];
            }
            curH = h;
        }
        // build Z for this batch (2048 elems / 256 threads = 8 each)
        {
            const float* s1p = g_S1 + b * F_SZ;
#pragma unroll
            for (int rep = 0; rep < 8; rep++)
                z_elem(sm + SM_Z, q2, s1p, rep * 256 + tid);
        }
        __syncthreads();

        // ---- mainloop: 16 k-iters, warp tile 32x32 ----
        float acc[8][4];
#pragma unroll
        for (int i = 0; i < 8; i++)
#pragma unroll
            for (int q = 0; q < 4; q++) acc[i][q] = 0.f;

#pragma unroll
        for (int k = 0; k < 16; k++) {
            uint32_t kA = (uint32_t)k * 32;
            uint32_t kB = (uint32_t)k * 16 * Z_RB;
            uint32_t a0[4], a1[4], bq0[4], bq1[4];
            LDSM4(a0, aBase + kA);
            LDSM4(a1, aBase + 16 * A_RB + kA);
            LDSM4T(bq0, bBase + kB);
            LDSM4T(bq1, bBase + kB + 32);

            HMMA(acc[0], a0, bq0[0], bq0[1]);
            HMMA(acc[1], a0, bq0[2], bq0[3]);
            HMMA(acc[2], a0, bq1[0], bq1[1]);
            HMMA(acc[3], a0, bq1[2], bq1[3]);
            HMMA(acc[4], a1, bq0[0], bq0[1]);
            HMMA(acc[5], a1, bq0[2], bq0[3]);
            HMMA(acc[6], a1, bq1[0], bq1[1]);
            HMMA(acc[7], a1, bq1[2], bq1[3]);
        }

        // ---- epilogue: scale by SA, store ----
        const float* sap = g_SA + b * F_SZ + h * 128;
        float* ob = out + (size_t)b * NFULL + h * 128 * D_SZ;
#pragma unroll
        for (int mt = 0; mt < 2; mt++) {
            int r0 = m0 + mt * 16 + g;
            float f0 = __ldg(sap + r0), f1 = __ldg(sap + r0 + 8);
#pragma unroll
            for (int nt = 0; nt < 4; nt++) {
                float* a = acc[mt * 4 + nt];
                int col = n0 + nt * 8 + 2 * t4;
                *(float2*)(ob + r0 * 64 + col) =
                    make_float2(a[0] * f0, a[1] * f0);
                *(float2*)(ob + (r0 + 8) * 64 + col) =
                    make_float2(a[2] * f1, a[3] * f1);
            }
        }
    }
}

// ---------------- launch ----------------
extern "C" void kernel_launch(void* const* d_in, const int* in_sizes, int n_in,
                              void* d_out, int out_size) {
    const float *feature = nullptr, *indicator = nullptr;
    const float *Wqk = nullptr, *Wqkv = nullptr;
    for (int k = 0; k < n_in; k++) {
        switch (in_sizes[k]) {
            case B_SZ * F_SZ * D_SZ: feature   = (const float*)d_in[k]; break;
            case F_SZ * D_SZ:        indicator = (const float*)d_in[k]; break;
            case 2 * D_SZ * D_SZ:    Wqk       = (const float*)d_in[k]; break;
            case 3 * D_SZ * D_SZ:    Wqkv      = (const float*)d_in[k]; break;
        }
    }
    float* out = (float*)d_out;

    cudaFuncSetAttribute(k_main, cudaFuncAttributeMaxDynamicSharedMemorySize,
                         SMEM_TOTAL);

    k_qkv<<<dim3(64, 5), 256>>>(indicator, Wqk, Wqkv);
    k_prep<<<768, 256>>>(feature);
    k_main<<<GRID_MAIN, 256, SMEM_TOTAL>>>(out);
}